// round 5
// baseline (speedup 1.0000x reference)
#include <cuda_runtime.h>
#include <math.h>

#define Bb   2
#define Ss   2048
#define Hh   2048          // HID
#define NHh  16
#define HDd  128
#define NR   (Bb * Ss)     // 4096
#define QN   (3 * NHh * HDd) // 6144

// ---------------- scratch (device globals; zero allocations) ---------------------
__device__ float d_qkv[(size_t)NR * QN];
__device__ float d_qh[(size_t)Bb * NHh * Ss * HDd];   // [B][NH][S][HD]
__device__ float d_kh[(size_t)Bb * NHh * Ss * HDd];
__device__ float d_vh[(size_t)Bb * NHh * Ss * HDd];
__device__ float d_oh[(size_t)NR * Hh];               // [B*S][NH*HD]

// ------------- GEMM v2: C[M,N] = A[M,K] * W[N,K]^T, scalar, 64x64 tiles ----------
__global__ __launch_bounds__(256)
void gemm_v2(const float* __restrict__ A, const float* __restrict__ W,
             float* __restrict__ C, int M, int N, int K) {
    __shared__ float sA[64][17];
    __shared__ float sB[64][17];
    const int tid = threadIdx.x;            // 0..255
    const int tx = tid % 16, ty = tid / 16; // 16x16
    const int m0 = blockIdx.y * 64, n0 = blockIdx.x * 64;

    float acc[4][4];
    for (int i = 0; i < 4; i++)
        for (int j = 0; j < 4; j++) acc[i][j] = 0.0f;

    for (int k0 = 0; k0 < K; k0 += 16) {
        for (int t = tid; t < 64 * 16; t += 256) {
            int r = t >> 4, c = t & 15;
            sA[r][c] = A[(size_t)(m0 + r) * K + k0 + c];
            sB[r][c] = W[(size_t)(n0 + r) * K + k0 + c];
        }
        __syncthreads();
        for (int kk = 0; kk < 16; kk++) {
            float a0 = sA[ty * 4 + 0][kk], a1 = sA[ty * 4 + 1][kk];
            float a2 = sA[ty * 4 + 2][kk], a3 = sA[ty * 4 + 3][kk];
            float b0 = sB[tx * 4 + 0][kk], b1 = sB[tx * 4 + 1][kk];
            float b2 = sB[tx * 4 + 2][kk], b3 = sB[tx * 4 + 3][kk];
            acc[0][0] += a0 * b0; acc[0][1] += a0 * b1; acc[0][2] += a0 * b2; acc[0][3] += a0 * b3;
            acc[1][0] += a1 * b0; acc[1][1] += a1 * b1; acc[1][2] += a1 * b2; acc[1][3] += a1 * b3;
            acc[2][0] += a2 * b0; acc[2][1] += a2 * b1; acc[2][2] += a2 * b2; acc[2][3] += a2 * b3;
            acc[3][0] += a3 * b0; acc[3][1] += a3 * b1; acc[3][2] += a3 * b2; acc[3][3] += a3 * b3;
        }
        __syncthreads();
    }
    for (int i = 0; i < 4; i++)
        for (int j = 0; j < 4; j++)
            C[(size_t)(m0 + ty * 4 + i) * N + n0 + tx * 4 + j] = acc[i][j];
}

// ------------- RMSNorm(flat 2048) + RoPE + scatter, scalar + tree reductions -----
__global__ __launch_bounds__(256)
void rmsrope_v2(const float* __restrict__ qw, const float* __restrict__ kw) {
    const int row = blockIdx.x;             // b*S + s
    const int b = row / Ss, s = row - b * Ss;
    const int tid = threadIdx.x;            // 0..255
    const float* base = d_qkv + (size_t)row * QN;

    __shared__ float red[256];
    __shared__ float scl[2];

    // --- q sum of squares ---
    float acc = 0.0f;
    for (int i = tid; i < 2048; i += 256) { float v = base[i]; acc += v * v; }
    red[tid] = acc;
    __syncthreads();
    for (int st = 128; st > 0; st >>= 1) {
        if (tid < st) red[tid] += red[tid + st];
        __syncthreads();
    }
    if (tid == 0) scl[0] = 1.0f / sqrtf(red[0] / 2048.0f + 1e-5f);
    __syncthreads();

    // --- k sum of squares ---
    acc = 0.0f;
    for (int i = tid; i < 2048; i += 256) { float v = base[2048 + i]; acc += v * v; }
    red[tid] = acc;
    __syncthreads();
    for (int st = 128; st > 0; st >>= 1) {
        if (tid < st) red[tid] += red[tid + st];
        __syncthreads();
    }
    if (tid == 0) scl[1] = 1.0f / sqrtf(red[0] / 2048.0f + 1e-5f);
    __syncthreads();

    const float rq = scl[0], rk = scl[1];

    // --- rope (rotate-half) + scatter to [B][NH][S][HD] ---
    for (int p = tid; p < NHh * 64; p += 256) {
        int h = p / 64, i = p - h * 64;     // head, pair index < 64
        float inv_freq = 1.0f / powf(10000.0f, (float)i / 64.0f);
        float ang = (float)s * inv_freq;
        float cv = cosf(ang), sv = sinf(ang);
        int i1 = h * 128 + i, i2 = i1 + 64;
        float q1 = base[i1] * rq * qw[i1];
        float q2 = base[i2] * rq * qw[i2];
        float k1 = base[2048 + i1] * rk * kw[i1];
        float k2 = base[2048 + i2] * rk * kw[i2];
        size_t o = (((size_t)b * NHh + h) * Ss + s) * HDd;
        d_qh[o + i]      = q1 * cv - q2 * sv;
        d_qh[o + i + 64] = q2 * cv + q1 * sv;
        d_kh[o + i]      = k1 * cv - k2 * sv;
        d_kh[o + i + 64] = k2 * cv + k1 * sv;
    }
    for (int e = tid; e < 2048; e += 256) {
        int h = e / 128, dd = e - h * 128;
        d_vh[(((size_t)b * NHh + h) * Ss + s) * HDd + dd] = base[4096 + e];
    }
}

// ------------- causal attention: block per (b,h,q), two-pass, tree reductions ----
__global__ __launch_bounds__(128)
void attn_v2() {
    const int q = blockIdx.x, h = blockIdx.y, b = blockIdx.z;
    const int tid = threadIdx.x;            // 0..127

    __shared__ float qs[HDd];
    __shared__ float sc[Ss];
    __shared__ float red[128];
    __shared__ float stat[2];

    const size_t hb = ((size_t)b * NHh + h) * Ss;
    qs[tid] = d_qh[(hb + q) * HDd + tid];
    __syncthreads();

    const float scale = 1.0f / sqrtf((float)HDd);

    // pass 1: scores
    for (int j = tid; j <= q; j += 128) {
        const float* kr = d_kh + (hb + j) * HDd;
        float sv = 0.0f;
        for (int t = 0; t < HDd; t++) sv += qs[t] * kr[t];
        sc[j] = sv * scale;
    }
    __syncthreads();

    // row max
    float m = -3.4e38f;
    for (int j = tid; j <= q; j += 128) m = fmaxf(m, sc[j]);
    red[tid] = m;
    __syncthreads();
    for (int st = 64; st > 0; st >>= 1) {
        if (tid < st) red[tid] = fmaxf(red[tid], red[tid + st]);
        __syncthreads();
    }
    if (tid == 0) stat[0] = red[0];
    __syncthreads();
    const float mx = stat[0];

    // exp + sum
    float ssum = 0.0f;
    for (int j = tid; j <= q; j += 128) {
        float p = expf(sc[j] - mx);
        sc[j] = p;
        ssum += p;
    }
    red[tid] = ssum;
    __syncthreads();
    for (int st = 64; st > 0; st >>= 1) {
        if (tid < st) red[tid] += red[tid + st];
        __syncthreads();
    }
    if (tid == 0) stat[1] = 1.0f / red[0];
    __syncthreads();
    const float sinv = stat[1];

    // pass 2: weighted V
    const float* vb = d_vh + hb * HDd + tid;
    float a = 0.0f;
    for (int j = 0; j <= q; j++) a += sc[j] * vb[(size_t)j * HDd];

    d_oh[((size_t)b * Ss + q) * Hh + h * HDd + tid] = a * sinv;
}

// ---------------- launch ----------------------------------------------------------
// Inputs identified BY ELEMENT COUNT (robust to metadata ordering):
//   x: 8,388,608   w_in: 12,582,912   w_out: 4,194,304   norms: 2,048 each
extern "C" void kernel_launch(void* const* d_in, const int* in_sizes, int n_in,
                              void* d_out, int out_size) {
    const float* x     = nullptr;
    const float* w_in  = nullptr;
    const float* w_out = nullptr;
    const float* qw    = nullptr;
    const float* kw    = nullptr;

    for (int i = 0; i < n_in; i++) {
        const float* p = (const float*)d_in[i];
        int n = in_sizes[i];
        if      (n == Bb * Ss * Hh)   x = p;
        else if (n == QN * Hh)        w_in = p;
        else if (n == Hh * NHh * HDd) w_out = p;
        else if (n == NHh * HDd) { if (!qw) qw = p; else kw = p; }
    }
    float* out = (float*)d_out;

    float *qkv_p = nullptr, *o_p = nullptr;
    cudaGetSymbolAddress((void**)&qkv_p, d_qkv);
    cudaGetSymbolAddress((void**)&o_p, d_oh);

    // 1) qkv = x @ w_in^T : [4096,2048] x [6144,2048]^T
    gemm_v2<<<dim3(QN / 64, NR / 64), 256>>>(x, w_in, qkv_p, NR, QN, Hh);

    // 2) rmsnorm(q,k) + rope + scatter
    rmsrope_v2<<<NR, 256>>>(qw, kw);

    // 3) causal attention
    attn_v2<<<dim3(Ss, NHh, Bb), 128>>>();

    // 4) out = O @ w_out^T : [4096,2048] x [2048,2048]^T
    gemm_v2<<<dim3(Hh / 64, NR / 64), 256>>>(o_p, w_out, out, NR, Hh, NHh * HDd);
}

// round 6
// speedup vs baseline: 4.4136x; 4.4136x over previous
#include <cuda_runtime.h>
#include <math.h>

#define Bb   2
#define Ss   2048
#define Hh   2048          // HID
#define NHh  16
#define HDd  128
#define NR   (Bb * Ss)     // 4096
#define QN   (3 * NHh * HDd) // 6144

// ---------------- scratch (device globals; zero allocations) ---------------------
__device__ float d_qkv[(size_t)NR * QN];
__device__ float d_qh[(size_t)Bb * NHh * Ss * HDd];   // [B][NH][S][HD]
__device__ float d_kh[(size_t)Bb * NHh * Ss * HDd];
__device__ float d_vh[(size_t)Bb * NHh * Ss * HDd];
__device__ float d_oh[(size_t)NR * Hh];               // [B*S][NH*HD]

// ------------- GEMM v3: C[M,N] = A[M,K] * W[N,K]^T, 128x128x16, float4 -----------
__global__ __launch_bounds__(256)
void gemm_v3(const float* __restrict__ A, const float* __restrict__ W,
             float* __restrict__ C, int M, int N, int K) {
    __shared__ float sA[16][132];   // [k][m], padded
    __shared__ float sB[16][132];   // [k][n], padded

    const int tid = threadIdx.x;          // 0..255
    const int tx = tid & 15, ty = tid >> 4;
    const int m0 = blockIdx.y * 128, n0 = blockIdx.x * 128;

    // load mapping: thread handles row lr = tid/2 (0..127), col half lc = (tid&1)*8
    const int lr = tid >> 1;
    const int lc = (tid & 1) << 3;
    const float* Ap = A + (size_t)(m0 + lr) * K + lc;
    const float* Wp = W + (size_t)(n0 + lr) * K + lc;

    float acc[8][8];
#pragma unroll
    for (int i = 0; i < 8; i++)
#pragma unroll
        for (int j = 0; j < 8; j++) acc[i][j] = 0.0f;

    for (int k0 = 0; k0 < K; k0 += 16) {
        float4 a0 = *(const float4*)(Ap + k0);
        float4 a1 = *(const float4*)(Ap + k0 + 4);
        float4 b0 = *(const float4*)(Wp + k0);
        float4 b1 = *(const float4*)(Wp + k0 + 4);
        sA[lc + 0][lr] = a0.x; sA[lc + 1][lr] = a0.y;
        sA[lc + 2][lr] = a0.z; sA[lc + 3][lr] = a0.w;
        sA[lc + 4][lr] = a1.x; sA[lc + 5][lr] = a1.y;
        sA[lc + 6][lr] = a1.z; sA[lc + 7][lr] = a1.w;
        sB[lc + 0][lr] = b0.x; sB[lc + 1][lr] = b0.y;
        sB[lc + 2][lr] = b0.z; sB[lc + 3][lr] = b0.w;
        sB[lc + 4][lr] = b1.x; sB[lc + 5][lr] = b1.y;
        sB[lc + 6][lr] = b1.z; sB[lc + 7][lr] = b1.w;
        __syncthreads();

#pragma unroll
        for (int kk = 0; kk < 16; kk++) {
            float ar[8], br[8];
            *(float4*)(ar)     = *(const float4*)&sA[kk][ty * 8];
            *(float4*)(ar + 4) = *(const float4*)&sA[kk][ty * 8 + 4];
            *(float4*)(br)     = *(const float4*)&sB[kk][tx * 8];
            *(float4*)(br + 4) = *(const float4*)&sB[kk][tx * 8 + 4];
#pragma unroll
            for (int i = 0; i < 8; i++)
#pragma unroll
                for (int j = 0; j < 8; j++)
                    acc[i][j] = fmaf(ar[i], br[j], acc[i][j]);
        }
        __syncthreads();
    }

#pragma unroll
    for (int i = 0; i < 8; i++) {
        float* cp = C + (size_t)(m0 + ty * 8 + i) * N + n0 + tx * 8;
        *(float4*)(cp)     = make_float4(acc[i][0], acc[i][1], acc[i][2], acc[i][3]);
        *(float4*)(cp + 4) = make_float4(acc[i][4], acc[i][5], acc[i][6], acc[i][7]);
    }
}

// ------------- RMSNorm(flat 2048) + RoPE + scatter  (UNCHANGED — verified) -------
__global__ __launch_bounds__(256)
void rmsrope_v2(const float* __restrict__ qw, const float* __restrict__ kw) {
    const int row = blockIdx.x;             // b*S + s
    const int b = row / Ss, s = row - b * Ss;
    const int tid = threadIdx.x;            // 0..255
    const float* base = d_qkv + (size_t)row * QN;

    __shared__ float red[256];
    __shared__ float scl[2];

    float acc = 0.0f;
    for (int i = tid; i < 2048; i += 256) { float v = base[i]; acc += v * v; }
    red[tid] = acc;
    __syncthreads();
    for (int st = 128; st > 0; st >>= 1) {
        if (tid < st) red[tid] += red[tid + st];
        __syncthreads();
    }
    if (tid == 0) scl[0] = 1.0f / sqrtf(red[0] / 2048.0f + 1e-5f);
    __syncthreads();

    acc = 0.0f;
    for (int i = tid; i < 2048; i += 256) { float v = base[2048 + i]; acc += v * v; }
    red[tid] = acc;
    __syncthreads();
    for (int st = 128; st > 0; st >>= 1) {
        if (tid < st) red[tid] += red[tid + st];
        __syncthreads();
    }
    if (tid == 0) scl[1] = 1.0f / sqrtf(red[0] / 2048.0f + 1e-5f);
    __syncthreads();

    const float rq = scl[0], rk = scl[1];

    for (int p = tid; p < NHh * 64; p += 256) {
        int h = p / 64, i = p - h * 64;
        float inv_freq = 1.0f / powf(10000.0f, (float)i / 64.0f);
        float ang = (float)s * inv_freq;
        float cv = cosf(ang), sv = sinf(ang);
        int i1 = h * 128 + i, i2 = i1 + 64;
        float q1 = base[i1] * rq * qw[i1];
        float q2 = base[i2] * rq * qw[i2];
        float k1 = base[2048 + i1] * rk * kw[i1];
        float k2 = base[2048 + i2] * rk * kw[i2];
        size_t o = (((size_t)b * NHh + h) * Ss + s) * HDd;
        d_qh[o + i]      = q1 * cv - q2 * sv;
        d_qh[o + i + 64] = q2 * cv + q1 * sv;
        d_kh[o + i]      = k1 * cv - k2 * sv;
        d_kh[o + i + 64] = k2 * cv + k1 * sv;
    }
    for (int e = tid; e < 2048; e += 256) {
        int h = e / 128, dd = e - h * 128;
        d_vh[(((size_t)b * NHh + h) * Ss + s) * HDd + dd] = base[4096 + e];
    }
}

// ------------- Flash attention v3 (fp32, causal), BQ=BK=64 ----------------------
// 256 threads as 16x16. Thread (tx,ty): score rows ty*4..+3, cols tx*4..+3;
// PV output dims tx*8..+7. QsT/KsT are dim-major [128][stride 68] for float4
// compute loads; transpose happens on (lane-consecutive-row) global loads, so
// smem stores are conflict-free.
#define TQ_STR 68
#define PS_STR 65
#define F_QT_OFF 0
#define F_KT_OFF (128 * TQ_STR)                  // 8704
#define F_V_OFF  (F_KT_OFF + 128 * TQ_STR)       // 17408
#define F_P_OFF  (F_V_OFF + 64 * HDd)            // 25600
#define F_SMEM_FLOATS (F_P_OFF + 64 * PS_STR)    // 29760
#define F_SMEM_BYTES  (F_SMEM_FLOATS * 4)        // 119040

__global__ __launch_bounds__(256)
void flash_v3() {
    extern __shared__ __align__(16) float sm[];
    float* QsT = sm + F_QT_OFF;   // [dim 0..127][qrow 0..63], stride 68
    float* KsT = sm + F_KT_OFF;   // [dim 0..127][krow 0..63], stride 68
    float* Vs  = sm + F_V_OFF;    // [krow 0..63][dim 0..127]
    float* Ps  = sm + F_P_OFF;    // [qrow 0..63][kcol 0..63], stride 65

    const int qb = blockIdx.x, h = blockIdx.y, b = blockIdx.z;
    const int tid = threadIdx.x;
    const int tx = tid & 15, ty = tid >> 4;
    const size_t head = ((size_t)b * NHh + h) * Ss;
    const float scale = 0.08838834764831845f;   // 1/sqrt(128)

    // Q load (transposed, scaled). i: r = i&63 (lane-consecutive), c4f = i>>6.
    {
        const float4* Qg = (const float4*)(d_qh + (head + (size_t)qb * 64) * HDd);
        for (int i = tid; i < 64 * 32; i += 256) {
            int r = i & 63, c4 = (i >> 6) << 2;
            float4 v = Qg[r * 32 + (i >> 6)];
            QsT[(c4 + 0) * TQ_STR + r] = v.x * scale;
            QsT[(c4 + 1) * TQ_STR + r] = v.y * scale;
            QsT[(c4 + 2) * TQ_STR + r] = v.z * scale;
            QsT[(c4 + 3) * TQ_STR + r] = v.w * scale;
        }
    }

    float m_i[4], l_i[4], acc[4][8];
#pragma unroll
    for (int r = 0; r < 4; r++) {
        m_i[r] = -1e30f; l_i[r] = 0.0f;
#pragma unroll
        for (int d = 0; d < 8; d++) acc[r][d] = 0.0f;
    }

    for (int kb = 0; kb <= qb; kb++) {
        __syncthreads();  // prior Ps/Vs/KsT reads done; Qs ready on first iter
        const float4* Kg = (const float4*)(d_kh + (head + (size_t)kb * 64) * HDd);
        const float4* Vg = (const float4*)(d_vh + (head + (size_t)kb * 64) * HDd);
        for (int i = tid; i < 64 * 32; i += 256) {
            int r = i & 63, c4 = (i >> 6) << 2;
            float4 v = Kg[r * 32 + (i >> 6)];
            KsT[(c4 + 0) * TQ_STR + r] = v.x;
            KsT[(c4 + 1) * TQ_STR + r] = v.y;
            KsT[(c4 + 2) * TQ_STR + r] = v.z;
            KsT[(c4 + 3) * TQ_STR + r] = v.w;
            ((float4*)Vs)[i] = Vg[i];   // row-major copy
        }
        __syncthreads();

        // ---- S = Q K^T (per-thread 4x4) ----
        float s4[4][4];
#pragma unroll
        for (int r = 0; r < 4; r++)
#pragma unroll
            for (int c = 0; c < 4; c++) s4[r][c] = 0.0f;

#pragma unroll 4
        for (int k = 0; k < HDd; k++) {
            float qv[4], kv[4];
            *(float4*)qv = *(const float4*)&QsT[k * TQ_STR + ty * 4];
            *(float4*)kv = *(const float4*)&KsT[k * TQ_STR + tx * 4];
#pragma unroll
            for (int r = 0; r < 4; r++)
#pragma unroll
                for (int c = 0; c < 4; c++)
                    s4[r][c] = fmaf(qv[r], kv[c], s4[r][c]);
        }

        if (kb == qb) {  // causal mask on diagonal tile
#pragma unroll
            for (int r = 0; r < 4; r++)
#pragma unroll
                for (int c = 0; c < 4; c++)
                    if (tx * 4 + c > ty * 4 + r) s4[r][c] = -1e30f;
        }

        // ---- online softmax over 16-lane row segments (same-ty group) ----
#pragma unroll
        for (int r = 0; r < 4; r++) {
            float mx = fmaxf(fmaxf(s4[r][0], s4[r][1]), fmaxf(s4[r][2], s4[r][3]));
#pragma unroll
            for (int o = 8; o; o >>= 1)
                mx = fmaxf(mx, __shfl_xor_sync(0xffffffffu, mx, o, 16));
            float m_new = fmaxf(m_i[r], mx);
            float corr = __expf(m_i[r] - m_new);
            float rs = 0.0f;
#pragma unroll
            for (int c = 0; c < 4; c++) {
                float p = __expf(s4[r][c] - m_new);
                Ps[(ty * 4 + r) * PS_STR + tx * 4 + c] = p;
                rs += p;
            }
#pragma unroll
            for (int o = 8; o; o >>= 1)
                rs += __shfl_xor_sync(0xffffffffu, rs, o, 16);
            l_i[r] = l_i[r] * corr + rs;
            m_i[r] = m_new;
#pragma unroll
            for (int d = 0; d < 8; d++) acc[r][d] *= corr;
        }
        __syncwarp();  // Ps rows for ty consumed only by same-warp threads

        // ---- acc += P V ----
#pragma unroll 2
        for (int j = 0; j < 64; j++) {
            float vv[8];
            *(float4*)(vv)     = *(const float4*)&Vs[j * HDd + tx * 8];
            *(float4*)(vv + 4) = *(const float4*)&Vs[j * HDd + tx * 8 + 4];
#pragma unroll
            for (int r = 0; r < 4; r++) {
                float p = Ps[(ty * 4 + r) * PS_STR + j];
#pragma unroll
                for (int d = 0; d < 8; d++)
                    acc[r][d] = fmaf(p, vv[d], acc[r][d]);
            }
        }
    }

#pragma unroll
    for (int r = 0; r < 4; r++) {
        float inv = 1.0f / l_i[r];
        size_t row = (size_t)b * Ss + (size_t)qb * 64 + ty * 4 + r;
        float* op = d_oh + row * Hh + h * HDd + tx * 8;
        *(float4*)(op)     = make_float4(acc[r][0] * inv, acc[r][1] * inv,
                                         acc[r][2] * inv, acc[r][3] * inv);
        *(float4*)(op + 4) = make_float4(acc[r][4] * inv, acc[r][5] * inv,
                                         acc[r][6] * inv, acc[r][7] * inv);
    }
}

// ---------------- launch ----------------------------------------------------------
// Inputs identified BY ELEMENT COUNT (robust to metadata ordering):
//   x: 8,388,608   w_in: 12,582,912   w_out: 4,194,304   norms: 2,048 each
extern "C" void kernel_launch(void* const* d_in, const int* in_sizes, int n_in,
                              void* d_out, int out_size) {
    const float* x     = nullptr;
    const float* w_in  = nullptr;
    const float* w_out = nullptr;
    const float* qw    = nullptr;
    const float* kw    = nullptr;

    for (int i = 0; i < n_in; i++) {
        const float* p = (const float*)d_in[i];
        int n = in_sizes[i];
        if      (n == Bb * Ss * Hh)   x = p;
        else if (n == QN * Hh)        w_in = p;
        else if (n == Hh * NHh * HDd) w_out = p;
        else if (n == NHh * HDd) { if (!qw) qw = p; else kw = p; }
    }
    float* out = (float*)d_out;

    float *qkv_p = nullptr, *o_p = nullptr;
    cudaGetSymbolAddress((void**)&qkv_p, d_qkv);
    cudaGetSymbolAddress((void**)&o_p, d_oh);

    cudaFuncSetAttribute(flash_v3,
                         cudaFuncAttributeMaxDynamicSharedMemorySize, F_SMEM_BYTES);

    // 1) qkv = x @ w_in^T : [4096,2048] x [6144,2048]^T
    gemm_v3<<<dim3(QN / 128, NR / 128), 256>>>(x, w_in, qkv_p, NR, QN, Hh);

    // 2) rmsnorm(q,k) + rope + scatter
    rmsrope_v2<<<NR, 256>>>(qw, kw);

    // 3) causal flash attention
    flash_v3<<<dim3(Ss / 64, NHh, Bb), 256, F_SMEM_BYTES>>>();

    // 4) out = O @ w_out^T : [4096,2048] x [2048,2048]^T
    gemm_v3<<<dim3(Hh / 128, NR / 128), 256>>>(o_p, w_out, out, NR, Hh, NHh * HDd);
}

// round 8
// speedup vs baseline: 13.7555x; 3.1166x over previous
#include <cuda_runtime.h>
#include <math.h>

#define Bb   2
#define Ss   2048
#define Hh   2048          // HID
#define NHh  16
#define HDd  128
#define NR   (Bb * Ss)     // 4096
#define QN   (3 * NHh * HDd) // 6144

// ---------------- scratch (device globals; zero allocations) ---------------------
__device__ float d_qkv[(size_t)NR * QN];
__device__ float d_qh[(size_t)Bb * NHh * Ss * HDd];   // [B][NH][S][HD]
__device__ float d_kh[(size_t)Bb * NHh * Ss * HDd];
__device__ float d_vh[(size_t)Bb * NHh * Ss * HDd];
__device__ float d_oh[(size_t)NR * Hh];               // [B*S][NH*HD]

// ---------------- tf32 helpers ---------------------------------------------------
__device__ __forceinline__ unsigned f2tf(float f) {
    unsigned u;
    asm("cvt.rna.tf32.f32 %0, %1;" : "=r"(u) : "f"(f));
    return u;
}

__device__ __forceinline__ void mma_tf32(float c[4], const unsigned a[4],
                                         const unsigned b[2]) {
    asm volatile(
        "mma.sync.aligned.m16n8k8.row.col.f32.tf32.tf32.f32 "
        "{%0,%1,%2,%3}, {%4,%5,%6,%7}, {%8,%9}, {%0,%1,%2,%3};\n"
        : "+f"(c[0]), "+f"(c[1]), "+f"(c[2]), "+f"(c[3])
        : "r"(a[0]), "r"(a[1]), "r"(a[2]), "r"(a[3]), "r"(b[0]), "r"(b[1]));
}

// ------------- GEMM tc: C[M,N] = A[M,K] * W[N,K]^T, tf32 tensor cores ------------
// 128x128x32 block, 8 warps, warp tile 64x32 via m16n8k8.
#define TS 36   // smem row stride (floats): frag LDS + STS.128 conflict-free

__global__ __launch_bounds__(256)
void gemm_tc(const float* __restrict__ A, const float* __restrict__ W,
             float* __restrict__ C, int M, int N, int K) {
    __shared__ unsigned sA[128][TS];
    __shared__ unsigned sB[128][TS];

    const int tid = threadIdx.x;
    const int wid = tid >> 5, lane = tid & 31;
    const int wm = wid & 1, wn = wid >> 1;    // warp grid 2 (m) x 4 (n)
    const int lr = lane >> 2, lc = lane & 3;
    const int m0 = blockIdx.y * 128, n0 = blockIdx.x * 128;

    float acc[4][4][4];
#pragma unroll
    for (int mf = 0; mf < 4; mf++)
#pragma unroll
        for (int nf = 0; nf < 4; nf++)
#pragma unroll
            for (int r = 0; r < 4; r++) acc[mf][nf][r] = 0.0f;

    // global load mapping: linear = i*256+tid; row = linear/8; col4 = (linear%8)*4
    const int glr = tid >> 3;           // base row step: 32 rows per 256-thread pass
    const int glc = (tid & 7) << 2;

    for (int k0 = 0; k0 < K; k0 += 32) {
#pragma unroll
        for (int i = 0; i < 4; i++) {
            int row = i * 32 + glr;
            float4 va = *(const float4*)(A + (size_t)(m0 + row) * K + k0 + glc);
            float4 vb = *(const float4*)(W + (size_t)(n0 + row) * K + k0 + glc);
            uint4 ua = make_uint4(f2tf(va.x), f2tf(va.y), f2tf(va.z), f2tf(va.w));
            uint4 ub = make_uint4(f2tf(vb.x), f2tf(vb.y), f2tf(vb.z), f2tf(vb.w));
            *(uint4*)&sA[row][glc] = ua;
            *(uint4*)&sB[row][glc] = ub;
        }
        __syncthreads();

#pragma unroll
        for (int ks = 0; ks < 4; ks++) {
            unsigned af[4][4], bf[4][2];
#pragma unroll
            for (int mf = 0; mf < 4; mf++) {
                int r = wm * 64 + mf * 16 + lr;
                af[mf][0] = sA[r][ks * 8 + lc];
                af[mf][1] = sA[r + 8][ks * 8 + lc];
                af[mf][2] = sA[r][ks * 8 + lc + 4];
                af[mf][3] = sA[r + 8][ks * 8 + lc + 4];
            }
#pragma unroll
            for (int nf = 0; nf < 4; nf++) {
                int n = wn * 32 + nf * 8 + lr;
                bf[nf][0] = sB[n][ks * 8 + lc];
                bf[nf][1] = sB[n][ks * 8 + lc + 4];
            }
#pragma unroll
            for (int mf = 0; mf < 4; mf++)
#pragma unroll
                for (int nf = 0; nf < 4; nf++)
                    mma_tf32(acc[mf][nf], af[mf], bf[nf]);
        }
        __syncthreads();
    }

#pragma unroll
    for (int mf = 0; mf < 4; mf++)
#pragma unroll
        for (int nf = 0; nf < 4; nf++) {
            int row = m0 + wm * 64 + mf * 16 + lr;
            int col = n0 + wn * 32 + nf * 8 + 2 * lc;
            *(float2*)&C[(size_t)row * N + col] =
                make_float2(acc[mf][nf][0], acc[mf][nf][1]);
            *(float2*)&C[(size_t)(row + 8) * N + col] =
                make_float2(acc[mf][nf][2], acc[mf][nf][3]);
        }
}

// ------------- RMSNorm(flat 2048) + RoPE + scatter  (UNCHANGED — verified) -------
__global__ __launch_bounds__(256)
void rmsrope_v2(const float* __restrict__ qw, const float* __restrict__ kw) {
    const int row = blockIdx.x;             // b*S + s
    const int b = row / Ss, s = row - b * Ss;
    const int tid = threadIdx.x;            // 0..255
    const float* base = d_qkv + (size_t)row * QN;

    __shared__ float red[256];
    __shared__ float scl[2];

    float acc = 0.0f;
    for (int i = tid; i < 2048; i += 256) { float v = base[i]; acc += v * v; }
    red[tid] = acc;
    __syncthreads();
    for (int st = 128; st > 0; st >>= 1) {
        if (tid < st) red[tid] += red[tid + st];
        __syncthreads();
    }
    if (tid == 0) scl[0] = 1.0f / sqrtf(red[0] / 2048.0f + 1e-5f);
    __syncthreads();

    acc = 0.0f;
    for (int i = tid; i < 2048; i += 256) { float v = base[2048 + i]; acc += v * v; }
    red[tid] = acc;
    __syncthreads();
    for (int st = 128; st > 0; st >>= 1) {
        if (tid < st) red[tid] += red[tid + st];
        __syncthreads();
    }
    if (tid == 0) scl[1] = 1.0f / sqrtf(red[0] / 2048.0f + 1e-5f);
    __syncthreads();

    const float rq = scl[0], rk = scl[1];

    for (int p = tid; p < NHh * 64; p += 256) {
        int h = p / 64, i = p - h * 64;
        float inv_freq = 1.0f / powf(10000.0f, (float)i / 64.0f);
        float ang = (float)s * inv_freq;
        float cv = cosf(ang), sv = sinf(ang);
        int i1 = h * 128 + i, i2 = i1 + 64;
        float q1 = base[i1] * rq * qw[i1];
        float q2 = base[i2] * rq * qw[i2];
        float k1 = base[2048 + i1] * rk * kw[i1];
        float k2 = base[2048 + i2] * rk * kw[i2];
        size_t o = (((size_t)b * NHh + h) * Ss + s) * HDd;
        d_qh[o + i]      = q1 * cv - q2 * sv;
        d_qh[o + i + 64] = q2 * cv + q1 * sv;
        d_kh[o + i]      = k1 * cv - k2 * sv;
        d_kh[o + i + 64] = k2 * cv + k1 * sv;
    }
    for (int e = tid; e < 2048; e += 256) {
        int h = e / 128, dd = e - h * 128;
        d_vh[(((size_t)b * NHh + h) * Ss + s) * HDd + dd] = base[4096 + e];
    }
}

// ------------- Flash attention v3 (fp32, causal)  (UNCHANGED — verified) ---------
#define TQ_STR 68
#define PS_STR 65
#define F_QT_OFF 0
#define F_KT_OFF (128 * TQ_STR)
#define F_V_OFF  (F_KT_OFF + 128 * TQ_STR)
#define F_P_OFF  (F_V_OFF + 64 * HDd)
#define F_SMEM_FLOATS (F_P_OFF + 64 * PS_STR)
#define F_SMEM_BYTES  (F_SMEM_FLOATS * 4)

__global__ __launch_bounds__(256)
void flash_v3() {
    extern __shared__ __align__(16) float sm[];
    float* QsT = sm + F_QT_OFF;
    float* KsT = sm + F_KT_OFF;
    float* Vs  = sm + F_V_OFF;
    float* Ps  = sm + F_P_OFF;

    const int qb = blockIdx.x, h = blockIdx.y, b = blockIdx.z;
    const int tid = threadIdx.x;
    const int tx = tid & 15, ty = tid >> 4;
    const size_t head = ((size_t)b * NHh + h) * Ss;
    const float scale = 0.08838834764831845f;

    {
        const float4* Qg = (const float4*)(d_qh + (head + (size_t)qb * 64) * HDd);
        for (int i = tid; i < 64 * 32; i += 256) {
            int r = i & 63, c4 = (i >> 6) << 2;
            float4 v = Qg[r * 32 + (i >> 6)];
            QsT[(c4 + 0) * TQ_STR + r] = v.x * scale;
            QsT[(c4 + 1) * TQ_STR + r] = v.y * scale;
            QsT[(c4 + 2) * TQ_STR + r] = v.z * scale;
            QsT[(c4 + 3) * TQ_STR + r] = v.w * scale;
        }
    }

    float m_i[4], l_i[4], acc[4][8];
#pragma unroll
    for (int r = 0; r < 4; r++) {
        m_i[r] = -1e30f; l_i[r] = 0.0f;
#pragma unroll
        for (int d = 0; d < 8; d++) acc[r][d] = 0.0f;
    }

    for (int kb = 0; kb <= qb; kb++) {
        __syncthreads();
        const float4* Kg = (const float4*)(d_kh + (head + (size_t)kb * 64) * HDd);
        const float4* Vg = (const float4*)(d_vh + (head + (size_t)kb * 64) * HDd);
        for (int i = tid; i < 64 * 32; i += 256) {
            int r = i & 63, c4 = (i >> 6) << 2;
            float4 v = Kg[r * 32 + (i >> 6)];
            KsT[(c4 + 0) * TQ_STR + r] = v.x;
            KsT[(c4 + 1) * TQ_STR + r] = v.y;
            KsT[(c4 + 2) * TQ_STR + r] = v.z;
            KsT[(c4 + 3) * TQ_STR + r] = v.w;
            ((float4*)Vs)[i] = Vg[i];
        }
        __syncthreads();

        float s4[4][4];
#pragma unroll
        for (int r = 0; r < 4; r++)
#pragma unroll
            for (int c = 0; c < 4; c++) s4[r][c] = 0.0f;

#pragma unroll 4
        for (int k = 0; k < HDd; k++) {
            float qv[4], kv[4];
            *(float4*)qv = *(const float4*)&QsT[k * TQ_STR + ty * 4];
            *(float4*)kv = *(const float4*)&KsT[k * TQ_STR + tx * 4];
#pragma unroll
            for (int r = 0; r < 4; r++)
#pragma unroll
                for (int c = 0; c < 4; c++)
                    s4[r][c] = fmaf(qv[r], kv[c], s4[r][c]);
        }

        if (kb == qb) {
#pragma unroll
            for (int r = 0; r < 4; r++)
#pragma unroll
                for (int c = 0; c < 4; c++)
                    if (tx * 4 + c > ty * 4 + r) s4[r][c] = -1e30f;
        }

#pragma unroll
        for (int r = 0; r < 4; r++) {
            float mx = fmaxf(fmaxf(s4[r][0], s4[r][1]), fmaxf(s4[r][2], s4[r][3]));
#pragma unroll
            for (int o = 8; o; o >>= 1)
                mx = fmaxf(mx, __shfl_xor_sync(0xffffffffu, mx, o, 16));
            float m_new = fmaxf(m_i[r], mx);
            float corr = __expf(m_i[r] - m_new);
            float rs = 0.0f;
#pragma unroll
            for (int c = 0; c < 4; c++) {
                float p = __expf(s4[r][c] - m_new);
                Ps[(ty * 4 + r) * PS_STR + tx * 4 + c] = p;
                rs += p;
            }
#pragma unroll
            for (int o = 8; o; o >>= 1)
                rs += __shfl_xor_sync(0xffffffffu, rs, o, 16);
            l_i[r] = l_i[r] * corr + rs;
            m_i[r] = m_new;
#pragma unroll
            for (int d = 0; d < 8; d++) acc[r][d] *= corr;
        }
        __syncwarp();

#pragma unroll 2
        for (int j = 0; j < 64; j++) {
            float vv[8];
            *(float4*)(vv)     = *(const float4*)&Vs[j * HDd + tx * 8];
            *(float4*)(vv + 4) = *(const float4*)&Vs[j * HDd + tx * 8 + 4];
#pragma unroll
            for (int r = 0; r < 4; r++) {
                float p = Ps[(ty * 4 + r) * PS_STR + j];
#pragma unroll
                for (int d = 0; d < 8; d++)
                    acc[r][d] = fmaf(p, vv[d], acc[r][d]);
            }
        }
    }

#pragma unroll
    for (int r = 0; r < 4; r++) {
        float inv = 1.0f / l_i[r];
        size_t row = (size_t)b * Ss + (size_t)qb * 64 + ty * 4 + r;
        float* op = d_oh + row * Hh + h * HDd + tx * 8;
        *(float4*)(op)     = make_float4(acc[r][0] * inv, acc[r][1] * inv,
                                         acc[r][2] * inv, acc[r][3] * inv);
        *(float4*)(op + 4) = make_float4(acc[r][4] * inv, acc[r][5] * inv,
                                         acc[r][6] * inv, acc[r][7] * inv);
    }
}

// ---------------- launch ----------------------------------------------------------
extern "C" void kernel_launch(void* const* d_in, const int* in_sizes, int n_in,
                              void* d_out, int out_size) {
    const float* x     = nullptr;
    const float* w_in  = nullptr;
    const float* w_out = nullptr;
    const float* qw    = nullptr;
    const float* kw    = nullptr;

    for (int i = 0; i < n_in; i++) {
        const float* p = (const float*)d_in[i];
        int n = in_sizes[i];
        if      (n == Bb * Ss * Hh)   x = p;
        else if (n == QN * Hh)        w_in = p;
        else if (n == Hh * NHh * HDd) w_out = p;
        else if (n == NHh * HDd) { if (!qw) qw = p; else kw = p; }
    }
    float* out = (float*)d_out;

    float *qkv_p = nullptr, *o_p = nullptr;
    cudaGetSymbolAddress((void**)&qkv_p, d_qkv);
    cudaGetSymbolAddress((void**)&o_p, d_oh);

    cudaFuncSetAttribute(flash_v3,
                         cudaFuncAttributeMaxDynamicSharedMemorySize, F_SMEM_BYTES);

    // 1) qkv = x @ w_in^T : [4096,2048] x [6144,2048]^T  (tf32 tensor cores)
    gemm_tc<<<dim3(QN / 128, NR / 128), 256>>>(x, w_in, qkv_p, NR, QN, Hh);

    // 2) rmsnorm(q,k) + rope + scatter
    rmsrope_v2<<<NR, 256>>>(qw, kw);

    // 3) causal flash attention (fp32)
    flash_v3<<<dim3(Ss / 64, NHh, Bb), 256, F_SMEM_BYTES>>>();

    // 4) out = O @ w_out^T : [4096,2048] x [2048,2048]^T  (tf32 tensor cores)
    gemm_tc<<<dim3(Hh / 128, NR / 128), 256>>>(o_p, w_out, out, NR, Hh, NHh * HDd);
}

// round 9
// speedup vs baseline: 22.0882x; 1.6058x over previous
#include <cuda_runtime.h>
#include <math.h>

#define Bb   2
#define Ss   2048
#define Hh   2048          // HID
#define NHh  16
#define HDd  128
#define NR   (Bb * Ss)     // 4096
#define QN   (3 * NHh * HDd) // 6144

// ---------------- scratch (device globals; zero allocations) ---------------------
__device__ float d_qkv[(size_t)NR * QN];
__device__ float d_qh[(size_t)Bb * NHh * Ss * HDd];   // [B][NH][S][HD]
__device__ float d_kh[(size_t)Bb * NHh * Ss * HDd];
__device__ float d_vh[(size_t)Bb * NHh * Ss * HDd];
__device__ float d_oh[(size_t)NR * Hh];               // [B*S][NH*HD]

// ---------------- tf32 helpers ---------------------------------------------------
__device__ __forceinline__ unsigned f2tf(float f) {
    unsigned u;
    asm("cvt.rna.tf32.f32 %0, %1;" : "=r"(u) : "f"(f));
    return u;
}

__device__ __forceinline__ void mma_tf32(float c[4], const unsigned a[4],
                                         const unsigned b[2]) {
    asm volatile(
        "mma.sync.aligned.m16n8k8.row.col.f32.tf32.tf32.f32 "
        "{%0,%1,%2,%3}, {%4,%5,%6,%7}, {%8,%9}, {%0,%1,%2,%3};\n"
        : "+f"(c[0]), "+f"(c[1]), "+f"(c[2]), "+f"(c[3])
        : "r"(a[0]), "r"(a[1]), "r"(a[2]), "r"(a[3]), "r"(b[0]), "r"(b[1]));
}

// ------------- GEMM tc: C[M,N] = A[M,K] * W[N,K]^T, tf32 (UNCHANGED) -------------
#define TS 36

__global__ __launch_bounds__(256)
void gemm_tc(const float* __restrict__ A, const float* __restrict__ W,
             float* __restrict__ C, int M, int N, int K) {
    __shared__ unsigned sA[128][TS];
    __shared__ unsigned sB[128][TS];

    const int tid = threadIdx.x;
    const int wid = tid >> 5, lane = tid & 31;
    const int wm = wid & 1, wn = wid >> 1;
    const int lr = lane >> 2, lc = lane & 3;
    const int m0 = blockIdx.y * 128, n0 = blockIdx.x * 128;

    float acc[4][4][4];
#pragma unroll
    for (int mf = 0; mf < 4; mf++)
#pragma unroll
        for (int nf = 0; nf < 4; nf++)
#pragma unroll
            for (int r = 0; r < 4; r++) acc[mf][nf][r] = 0.0f;

    const int glr = tid >> 3;
    const int glc = (tid & 7) << 2;

    for (int k0 = 0; k0 < K; k0 += 32) {
#pragma unroll
        for (int i = 0; i < 4; i++) {
            int row = i * 32 + glr;
            float4 va = *(const float4*)(A + (size_t)(m0 + row) * K + k0 + glc);
            float4 vb = *(const float4*)(W + (size_t)(n0 + row) * K + k0 + glc);
            uint4 ua = make_uint4(f2tf(va.x), f2tf(va.y), f2tf(va.z), f2tf(va.w));
            uint4 ub = make_uint4(f2tf(vb.x), f2tf(vb.y), f2tf(vb.z), f2tf(vb.w));
            *(uint4*)&sA[row][glc] = ua;
            *(uint4*)&sB[row][glc] = ub;
        }
        __syncthreads();

#pragma unroll
        for (int ks = 0; ks < 4; ks++) {
            unsigned af[4][4], bf[4][2];
#pragma unroll
            for (int mf = 0; mf < 4; mf++) {
                int r = wm * 64 + mf * 16 + lr;
                af[mf][0] = sA[r][ks * 8 + lc];
                af[mf][1] = sA[r + 8][ks * 8 + lc];
                af[mf][2] = sA[r][ks * 8 + lc + 4];
                af[mf][3] = sA[r + 8][ks * 8 + lc + 4];
            }
#pragma unroll
            for (int nf = 0; nf < 4; nf++) {
                int n = wn * 32 + nf * 8 + lr;
                bf[nf][0] = sB[n][ks * 8 + lc];
                bf[nf][1] = sB[n][ks * 8 + lc + 4];
            }
#pragma unroll
            for (int mf = 0; mf < 4; mf++)
#pragma unroll
                for (int nf = 0; nf < 4; nf++)
                    mma_tf32(acc[mf][nf], af[mf], bf[nf]);
        }
        __syncthreads();
    }

#pragma unroll
    for (int mf = 0; mf < 4; mf++)
#pragma unroll
        for (int nf = 0; nf < 4; nf++) {
            int row = m0 + wm * 64 + mf * 16 + lr;
            int col = n0 + wn * 32 + nf * 8 + 2 * lc;
            *(float2*)&C[(size_t)row * N + col] =
                make_float2(acc[mf][nf][0], acc[mf][nf][1]);
            *(float2*)&C[(size_t)(row + 8) * N + col] =
                make_float2(acc[mf][nf][2], acc[mf][nf][3]);
        }
}

// ------------- RMSNorm(flat 2048) + RoPE + scatter  (UNCHANGED — verified) -------
__global__ __launch_bounds__(256)
void rmsrope_v2(const float* __restrict__ qw, const float* __restrict__ kw) {
    const int row = blockIdx.x;
    const int b = row / Ss, s = row - b * Ss;
    const int tid = threadIdx.x;
    const float* base = d_qkv + (size_t)row * QN;

    __shared__ float red[256];
    __shared__ float scl[2];

    float acc = 0.0f;
    for (int i = tid; i < 2048; i += 256) { float v = base[i]; acc += v * v; }
    red[tid] = acc;
    __syncthreads();
    for (int st = 128; st > 0; st >>= 1) {
        if (tid < st) red[tid] += red[tid + st];
        __syncthreads();
    }
    if (tid == 0) scl[0] = 1.0f / sqrtf(red[0] / 2048.0f + 1e-5f);
    __syncthreads();

    acc = 0.0f;
    for (int i = tid; i < 2048; i += 256) { float v = base[2048 + i]; acc += v * v; }
    red[tid] = acc;
    __syncthreads();
    for (int st = 128; st > 0; st >>= 1) {
        if (tid < st) red[tid] += red[tid + st];
        __syncthreads();
    }
    if (tid == 0) scl[1] = 1.0f / sqrtf(red[0] / 2048.0f + 1e-5f);
    __syncthreads();

    const float rq = scl[0], rk = scl[1];

    for (int p = tid; p < NHh * 64; p += 256) {
        int h = p / 64, i = p - h * 64;
        float inv_freq = 1.0f / powf(10000.0f, (float)i / 64.0f);
        float ang = (float)s * inv_freq;
        float cv = cosf(ang), sv = sinf(ang);
        int i1 = h * 128 + i, i2 = i1 + 64;
        float q1 = base[i1] * rq * qw[i1];
        float q2 = base[i2] * rq * qw[i2];
        float k1 = base[2048 + i1] * rk * kw[i1];
        float k2 = base[2048 + i2] * rk * kw[i2];
        size_t o = (((size_t)b * NHh + h) * Ss + s) * HDd;
        d_qh[o + i]      = q1 * cv - q2 * sv;
        d_qh[o + i + 64] = q2 * cv + q1 * sv;
        d_kh[o + i]      = k1 * cv - k2 * sv;
        d_kh[o + i + 64] = k2 * cv + k1 * sv;
    }
    for (int e = tid; e < 2048; e += 256) {
        int h = e / 128, dd = e - h * 128;
        d_vh[(((size_t)b * NHh + h) * Ss + s) * HDd + dd] = base[4096 + e];
    }
}

// ------------- Flash attention tc (tf32 tensor cores, causal) --------------------
// BQ=128, BK=64, 8 warps; warp w owns q rows [w*16, w*16+16).
// Smem (floats): KsT[128][72] @0 | Vs[64][136] @9216 | (Qstage[128][132] @0,
// prologue only, aliases KsT+Vs) | Ps[128][68] @17920.  Total 26624 f = 104 KB.
#define KT_STR 72
#define VS_STR 136
#define PS2_STR 68
#define QS_STR 132
#define FK_OFF 0
#define FV_OFF (128 * KT_STR)                 // 9216
#define FP_OFF (FV_OFF + 64 * VS_STR)         // 17920
#define FT_SMEM_U (FP_OFF + 128 * PS2_STR)    // 26624
#define FT_SMEM_BYTES (FT_SMEM_U * 4)

__global__ __launch_bounds__(256, 1)
void flash_tc() {
    extern __shared__ __align__(16) unsigned smu[];
    unsigned* KsT = smu + FK_OFF;   // [d 0..127][key 0..63] tf32
    unsigned* Vs  = smu + FV_OFF;   // [key 0..63][d 0..127] tf32
    unsigned* Qst = smu + FK_OFF;   // prologue alias [qrow 0..127][d 0..127]
    unsigned* Ps  = smu + FP_OFF;   // [qrow 0..127][key 0..63] tf32

    const int qb = blockIdx.x, h = blockIdx.y, b = blockIdx.z;
    const int tid = threadIdx.x;
    const int w = tid >> 5, lane = tid & 31;
    const int lr = lane >> 2, lc = lane & 3;
    const size_t head = ((size_t)b * NHh + h) * Ss;
    const float scale = 0.08838834764831845f;   // 1/sqrt(128)

    // ---- prologue: Q tile -> smem (scaled tf32), then frags -> registers --------
    {
        const float4* Qg = (const float4*)(d_qh + (head + (size_t)qb * 128) * HDd);
        for (int i = tid; i < 128 * 32; i += 256) {
            int r = i >> 5, c = i & 31;
            float4 v = Qg[i];
            Qst[r * QS_STR + 4 * c + 0] = f2tf(v.x * scale);
            Qst[r * QS_STR + 4 * c + 1] = f2tf(v.y * scale);
            Qst[r * QS_STR + 4 * c + 2] = f2tf(v.z * scale);
            Qst[r * QS_STR + 4 * c + 3] = f2tf(v.w * scale);
        }
    }
    __syncthreads();

    unsigned qa[16][4];
#pragma unroll
    for (int ks = 0; ks < 16; ks++) {
        int r0 = (w * 16 + lr) * QS_STR, r1 = (w * 16 + lr + 8) * QS_STR;
        qa[ks][0] = Qst[r0 + ks * 8 + lc];
        qa[ks][1] = Qst[r1 + ks * 8 + lc];
        qa[ks][2] = Qst[r0 + ks * 8 + lc + 4];
        qa[ks][3] = Qst[r1 + ks * 8 + lc + 4];
    }
    __syncthreads();   // frags latched; smem free for K/V

    float oacc[16][4];
#pragma unroll
    for (int nf = 0; nf < 16; nf++)
#pragma unroll
        for (int r = 0; r < 4; r++) oacc[nf][r] = 0.0f;
    float m_i[2] = {-1e30f, -1e30f}, l_i[2] = {0.0f, 0.0f};

    const int kb_max = 2 * qb + 1;
    for (int kb = 0; kb <= kb_max; kb++) {
        __syncthreads();   // prior KsT/Vs reads done
        const float4* Kg = (const float4*)(d_kh + (head + (size_t)kb * 64) * HDd);
        const float4* Vg = (const float4*)(d_vh + (head + (size_t)kb * 64) * HDd);
        for (int i = tid; i < 64 * 32; i += 256) {
            int rk = i & 63, ck = (i >> 6) << 2;     // K: transpose store
            float4 kv = Kg[rk * 32 + (i >> 6)];
            KsT[(ck + 0) * KT_STR + rk] = f2tf(kv.x);
            KsT[(ck + 1) * KT_STR + rk] = f2tf(kv.y);
            KsT[(ck + 2) * KT_STR + rk] = f2tf(kv.z);
            KsT[(ck + 3) * KT_STR + rk] = f2tf(kv.w);
            int rv = i >> 5, cv = i & 31;            // V: row-major store
            float4 vv = Vg[i];
            Vs[rv * VS_STR + 4 * cv + 0] = f2tf(vv.x);
            Vs[rv * VS_STR + 4 * cv + 1] = f2tf(vv.y);
            Vs[rv * VS_STR + 4 * cv + 2] = f2tf(vv.z);
            Vs[rv * VS_STR + 4 * cv + 3] = f2tf(vv.w);
        }
        __syncthreads();

        // ---- S = Q K^T : warp rows 16, cols 64 (8 n-frags), K=128 (16 steps) ----
        float sacc[8][4];
#pragma unroll
        for (int nf = 0; nf < 8; nf++)
#pragma unroll
            for (int r = 0; r < 4; r++) sacc[nf][r] = 0.0f;

#pragma unroll
        for (int ks = 0; ks < 16; ks++) {
            unsigned bf[8][2];
#pragma unroll
            for (int nf = 0; nf < 8; nf++) {
                bf[nf][0] = KsT[(ks * 8 + lc) * KT_STR + nf * 8 + lr];
                bf[nf][1] = KsT[(ks * 8 + lc + 4) * KT_STR + nf * 8 + lr];
            }
#pragma unroll
            for (int nf = 0; nf < 8; nf++)
                mma_tf32(sacc[nf], qa[ks], bf[nf]);
        }

        // ---- causal mask (only diagonal-adjacent tiles) ----
        if (kb >= 2 * qb) {
            int row0 = qb * 128 + w * 16 + lr;
            int row1 = row0 + 8;
#pragma unroll
            for (int nf = 0; nf < 8; nf++) {
                int col = kb * 64 + nf * 8 + 2 * lc;
                if (col > row0)     sacc[nf][0] = -1e30f;
                if (col + 1 > row0) sacc[nf][1] = -1e30f;
                if (col > row1)     sacc[nf][2] = -1e30f;
                if (col + 1 > row1) sacc[nf][3] = -1e30f;
            }
        }

        // ---- online softmax: thread owns rows lr (c0,c1) and lr+8 (c2,c3) ----
        float mx0 = -1e30f, mx1 = -1e30f;
#pragma unroll
        for (int nf = 0; nf < 8; nf++) {
            mx0 = fmaxf(mx0, fmaxf(sacc[nf][0], sacc[nf][1]));
            mx1 = fmaxf(mx1, fmaxf(sacc[nf][2], sacc[nf][3]));
        }
        mx0 = fmaxf(mx0, __shfl_xor_sync(0xffffffffu, mx0, 1));
        mx0 = fmaxf(mx0, __shfl_xor_sync(0xffffffffu, mx0, 2));
        mx1 = fmaxf(mx1, __shfl_xor_sync(0xffffffffu, mx1, 1));
        mx1 = fmaxf(mx1, __shfl_xor_sync(0xffffffffu, mx1, 2));

        float mn0 = fmaxf(m_i[0], mx0), mn1 = fmaxf(m_i[1], mx1);
        float corr0 = __expf(m_i[0] - mn0), corr1 = __expf(m_i[1] - mn1);
        m_i[0] = mn0; m_i[1] = mn1;

        float rs0 = 0.0f, rs1 = 0.0f;
        unsigned prow0 = (w * 16 + lr) * PS2_STR;
        unsigned prow1 = (w * 16 + lr + 8) * PS2_STR;
#pragma unroll
        for (int nf = 0; nf < 8; nf++) {
            float p0 = __expf(sacc[nf][0] - mn0);
            float p1 = __expf(sacc[nf][1] - mn0);
            float p2 = __expf(sacc[nf][2] - mn1);
            float p3 = __expf(sacc[nf][3] - mn1);
            rs0 += p0 + p1; rs1 += p2 + p3;
            *(uint2*)&Ps[prow0 + nf * 8 + 2 * lc] = make_uint2(f2tf(p0), f2tf(p1));
            *(uint2*)&Ps[prow1 + nf * 8 + 2 * lc] = make_uint2(f2tf(p2), f2tf(p3));
        }
        rs0 += __shfl_xor_sync(0xffffffffu, rs0, 1);
        rs0 += __shfl_xor_sync(0xffffffffu, rs0, 2);
        rs1 += __shfl_xor_sync(0xffffffffu, rs1, 1);
        rs1 += __shfl_xor_sync(0xffffffffu, rs1, 2);
        l_i[0] = l_i[0] * corr0 + rs0;
        l_i[1] = l_i[1] * corr1 + rs1;

#pragma unroll
        for (int nf = 0; nf < 16; nf++) {
            oacc[nf][0] *= corr0; oacc[nf][1] *= corr0;
            oacc[nf][2] *= corr1; oacc[nf][3] *= corr1;
        }
        __syncwarp();   // Ps rows are warp-private

        // ---- O += P V : M=16, N=128 (16 n-frags), K=64 (8 steps) ----
#pragma unroll
        for (int ks = 0; ks < 8; ks++) {
            unsigned pa[4];
            pa[0] = Ps[prow0 + ks * 8 + lc];
            pa[1] = Ps[prow1 + ks * 8 + lc];
            pa[2] = Ps[prow0 + ks * 8 + lc + 4];
            pa[3] = Ps[prow1 + ks * 8 + lc + 4];
#pragma unroll
            for (int nf = 0; nf < 16; nf++) {
                unsigned vb[2];
                vb[0] = Vs[(ks * 8 + lc) * VS_STR + nf * 8 + lr];
                vb[1] = Vs[(ks * 8 + lc + 4) * VS_STR + nf * 8 + lr];
                mma_tf32(oacc[nf], pa, vb);
            }
        }
    }

    // ---- epilogue ----
    float inv0 = 1.0f / l_i[0], inv1 = 1.0f / l_i[1];
    int row0 = qb * 128 + w * 16 + lr;
#pragma unroll
    for (int nf = 0; nf < 16; nf++) {
        int col = h * HDd + nf * 8 + 2 * lc;
        *(float2*)&d_oh[((size_t)b * Ss + row0) * Hh + col] =
            make_float2(oacc[nf][0] * inv0, oacc[nf][1] * inv0);
        *(float2*)&d_oh[((size_t)b * Ss + row0 + 8) * Hh + col] =
            make_float2(oacc[nf][2] * inv1, oacc[nf][3] * inv1);
    }
}

// ---------------- launch ----------------------------------------------------------
extern "C" void kernel_launch(void* const* d_in, const int* in_sizes, int n_in,
                              void* d_out, int out_size) {
    const float* x     = nullptr;
    const float* w_in  = nullptr;
    const float* w_out = nullptr;
    const float* qw    = nullptr;
    const float* kw    = nullptr;

    for (int i = 0; i < n_in; i++) {
        const float* p = (const float*)d_in[i];
        int n = in_sizes[i];
        if      (n == Bb * Ss * Hh)   x = p;
        else if (n == QN * Hh)        w_in = p;
        else if (n == Hh * NHh * HDd) w_out = p;
        else if (n == NHh * HDd) { if (!qw) qw = p; else kw = p; }
    }
    float* out = (float*)d_out;

    float *qkv_p = nullptr, *o_p = nullptr;
    cudaGetSymbolAddress((void**)&qkv_p, d_qkv);
    cudaGetSymbolAddress((void**)&o_p, d_oh);

    cudaFuncSetAttribute(flash_tc,
                         cudaFuncAttributeMaxDynamicSharedMemorySize, FT_SMEM_BYTES);

    // 1) qkv = x @ w_in^T  (tf32 tensor cores)
    gemm_tc<<<dim3(QN / 128, NR / 128), 256>>>(x, w_in, qkv_p, NR, QN, Hh);

    // 2) rmsnorm(q,k) + rope + scatter
    rmsrope_v2<<<NR, 256>>>(qw, kw);

    // 3) causal flash attention (tf32 tensor cores)
    flash_tc<<<dim3(Ss / 128, NHh, Bb), 256, FT_SMEM_BYTES>>>();

    // 4) out = O @ w_out^T  (tf32 tensor cores)
    gemm_tc<<<dim3(Hh / 128, NR / 128), 256>>>(o_p, w_out, out, NR, Hh, NHh * HDd);
}